// round 15
// baseline (speedup 1.0000x reference)
#include <cuda_runtime.h>
#include <cuda_fp16.h>
#include <cstdint>

static constexpr int B = 16, H = 256, W = 256;
static constexpr int CIN0 = 3, CMID = 16, COUT = 64;
static constexpr float BN_EPS = 1e-5f;

// h1/h2: fp16, stored as __half2 ci-pair planes: [b][ci/2][y][x] (uint32)
__device__ uint32_t g_h1[(size_t)B * (CMID / 2) * H * W];
__device__ uint32_t g_h2[(size_t)B * (CMID / 2) * H * W];
__device__ float g_stats[2 * COUT];
__device__ float g_scale[COUT];
__device__ float g_shift[COUT];

// ---- helpers ---------------------------------------------------------------
__device__ __forceinline__ uint32_t smem_u32(const void* p) {
    uint32_t a;
    asm("{ .reg .u64 t; cvta.to.shared.u64 t, %1; cvt.u32.u64 %0, t; }"
        : "=r"(a) : "l"(p));
    return a;
}
__device__ __forceinline__ void sts64(uint32_t a, uint32_t x, uint32_t y) {
    asm volatile("st.shared.v2.u32 [%0], {%1,%2};" :: "r"(a), "r"(x), "r"(y));
}
__device__ __forceinline__ void sts16(uint32_t a, uint16_t v) {
    asm volatile("st.shared.u16 [%0], %1;" :: "r"(a), "h"(v));
}
__device__ __forceinline__ uint32_t lds32(uint32_t a) {
    uint32_t v;
    asm volatile("ld.shared.b32 %0, [%1];" : "=r"(v) : "r"(a));
    return v;
}
__device__ __forceinline__ uint32_t packh2(float lo, float hi) {
    const __half h0 = __float2half_rn(lo), h1 = __float2half_rn(hi);
    return ((uint32_t)__half_as_ushort(h1) << 16) |
           (uint32_t)__half_as_ushort(h0);
}
// baseline-PTX fp16 tensor-core mma (sm_80+)
__device__ __forceinline__ void mma_f16(float d[4], const uint32_t a[4],
                                        const uint32_t b[2]) {
    asm volatile(
        "mma.sync.aligned.m16n8k16.row.col.f32.f16.f16.f32 "
        "{%0,%1,%2,%3},{%4,%5,%6,%7},{%8,%9},{%0,%1,%2,%3};"
        : "+f"(d[0]), "+f"(d[1]), "+f"(d[2]), "+f"(d[3])
        : "r"(a[0]), "r"(a[1]), "r"(a[2]), "r"(a[3]), "r"(b[0]), "r"(b[1]));
}

// ---- tensor-core 3x3 conv (16 in-ch), fp16 acts / split-fp16 weights -------
// A per input row UNSHIFTED: [130 xl][16 ci fp16], stride 48 B (conflict-free
// banks); dx shift = +ks*48 address offset. RING OF 8 rows (&7). B per dy:
// [CO][48 fp16], stride 112 B, hi + lo (weight residual). 2 MMAs/step.
// TWO output rows per barrier: B fragments feed both rows; A rows carried in
// registers across dy (A[y+dy] == next dy's A[y-1+dy']), so 4 A-row loads/ks.
static constexpr int AXS   = 48;
static constexpr int ASLOT = 132 * AXS;         // 6336 per row
static constexpr int BBASE = 8 * ASLOT;         // 50688
static constexpr int NY    = 8;
static constexpr int NITER = NY / 2;
static constexpr int NT    = 256;
static constexpr int NITEM = 520;               // 130 xl * 4 ci-groups

__device__ __forceinline__ void stage_load(const uint32_t* in, int b, int yin,
                                           int x0, int tid, uint32_t v[3][2]) {
    #pragma unroll
    for (int j = 0; j < 3; ++j) {
        v[j][0] = v[j][1] = 0;
        const int it = tid + j * NT;
        if (it >= NITEM) continue;
        const int xl = it >> 2, cig = it & 3, xin = x0 - 1 + xl;
        if (xin >= 0 && xin < W) {
            const uint32_t* p =
                in + (((size_t)b * 8 + cig * 2) * H + yin) * W + xin;
            v[j][0] = p[0];
            v[j][1] = p[(size_t)H * W];
        }
    }
}
__device__ __forceinline__ void stage_store(uint32_t s32, int yin, int tid,
                                            const uint32_t v[3][2]) {
    const uint32_t Ah = s32 + (uint32_t)(yin & 7) * ASLOT;
    #pragma unroll
    for (int j = 0; j < 3; ++j) {
        const int it = tid + j * NT;
        if (it >= NITEM) continue;
        const int xl = it >> 2, cig = it & 3;
        sts64(Ah + (uint32_t)(xl * AXS + cig * 8), v[j][0], v[j][1]);
    }
}

// Warp grid WM x WN, per-warp fragments MF x NF (per output row).
// WM*MF*16 == 128, WN*NF*8 == CO, WM*WN == 8 (256 threads).
template <int CO, int WM, int WN, int MF, int NF, bool STATS, bool OUTH2>
__global__ void __launch_bounds__(NT, 2)
conv_mma(const uint32_t* __restrict__ in, const float* __restrict__ wgt,
         void* __restrict__ outv) {
    static_assert(WM * MF * 16 == 128 && WN * NF * 8 == CO && WM * WN == 8, "");
    constexpr int BLO  = CO * 112;
    constexpr int BDY  = 2 * BLO;
    constexpr int SOFF = BBASE + 3 * BDY;

    extern __shared__ char sm[];
    const uint32_t s32 = smem_u32(sm);
    float* sstats = (float*)(sm + SOFF);
    const int tid = threadIdx.x, wid = tid >> 5, lid = tid & 31;
    const int g = lid >> 2, tig = lid & 3;
    int bid = blockIdx.x;
    const int xs = bid & 1, ys = (bid >> 1) & 31, b = bid >> 6;
    const int x0 = xs * 128, y0 = ys * NY;

    if (STATS && tid < 128) sstats[tid] = 0.f;
    for (int i = tid; i < CO * CMID * 9; i += NT) {   // weights -> B hi/lo
        const int dx = i % 3; int t = i / 3;
        const int dy = t % 3; t /= 3;
        const int ci = t & 15, co = t >> 4;
        const float v = wgt[((co * CMID + ci) * 3 + dy) * 3 + dx];
        const __half h = __float2half_rn(v);
        const __half l = __float2half_rn(v - __half2float(h));
        const uint32_t a = s32 + BBASE + dy * BDY + co * 112 + (dx * 16 + ci) * 2;
        sts16(a, (uint16_t)__half_as_ushort(h));
        sts16(a + BLO, (uint16_t)__half_as_ushort(l));
    }
    {   // prologue: rows y0-1 .. y0+2
        uint32_t pv[3][2];
        #pragma unroll 1
        for (int d = -1; d <= 2; ++d) {
            const int yin = y0 + d;
            if (yin < 0 || yin >= H) continue;
            stage_load(in, b, yin, x0, tid, pv);
            stage_store(s32, yin, tid, pv);
        }
    }
    __syncthreads();

    const int wm = wid % WM, wn = wid / WM;
    float sacc[NF][2] = {}, qacc[NF][2] = {};

    #pragma unroll 1
    for (int i = 0; i < NITER; ++i) {
        const int y = y0 + 2 * i;
        uint32_t pf0[3][2], pf1[3][2];
        const bool s3 = (i + 1 < NITER) && (y + 3 < H);
        const bool s4 = (i + 1 < NITER) && (y + 4 < H);
        if (s3) stage_load(in, b, y + 3, x0, tid, pf0);
        if (s4) stage_load(in, b, y + 4, x0, tid, pf1);

        float acc[2][MF][NF][4];
        #pragma unroll
        for (int r = 0; r < 2; ++r)
            #pragma unroll
            for (int mf = 0; mf < MF; ++mf)
                #pragma unroll
                for (int nf = 0; nf < NF; ++nf)
                    #pragma unroll
                    for (int q = 0; q < 4; ++q) acc[r][mf][nf][q] = 0.f;

        #pragma unroll
        for (int ks = 0; ks < 3; ++ks) {
            uint32_t ap[MF][4];                       // A[y-1+dy] (carried)
            bool vp = (y > 0);
            if (vp) {
                const uint32_t A0 = s32 + (uint32_t)((y - 1) & 7) * ASLOT;
                #pragma unroll
                for (int mf = 0; mf < MF; ++mf) {
                    const uint32_t r0 = A0 +
                        (uint32_t)((wm * (MF * 16) + mf * 16 + g + ks) * AXS +
                                   tig * 4);
                    const uint32_t r1 = r0 + 8 * AXS;
                    ap[mf][0] = lds32(r0);      ap[mf][1] = lds32(r1);
                    ap[mf][2] = lds32(r0 + 16); ap[mf][3] = lds32(r1 + 16);
                }
            }
            #pragma unroll
            for (int dy = 0; dy < 3; ++dy) {
                const int gc = y + dy;                // A row for output y+1
                const bool vc = (gc < H);
                uint32_t ac[MF][4];
                if (vc) {
                    const uint32_t A0 = s32 + (uint32_t)(gc & 7) * ASLOT;
                    #pragma unroll
                    for (int mf = 0; mf < MF; ++mf) {
                        const uint32_t r0 = A0 +
                            (uint32_t)((wm * (MF * 16) + mf * 16 + g + ks) * AXS +
                                       tig * 4);
                        const uint32_t r1 = r0 + 8 * AXS;
                        ac[mf][0] = lds32(r0);      ac[mf][1] = lds32(r1);
                        ac[mf][2] = lds32(r0 + 16); ac[mf][3] = lds32(r1 + 16);
                    }
                }
                uint32_t bh[NF][2], bl[NF][2];
                const uint32_t B0 = s32 + BBASE + dy * BDY;
                #pragma unroll
                for (int nf = 0; nf < NF; ++nf) {
                    const uint32_t c0 = B0 +
                        (uint32_t)((wn * (NF * 8) + nf * 8 + g) * 112 +
                                   ks * 32 + tig * 4);
                    bh[nf][0] = lds32(c0);        bh[nf][1] = lds32(c0 + 16);
                    bl[nf][0] = lds32(c0 + BLO);  bl[nf][1] = lds32(c0 + BLO + 16);
                }
                if (vp) {
                    #pragma unroll
                    for (int mf = 0; mf < MF; ++mf)
                        #pragma unroll
                        for (int nf = 0; nf < NF; ++nf) {
                            mma_f16(acc[0][mf][nf], ap[mf], bh[nf]);
                            mma_f16(acc[0][mf][nf], ap[mf], bl[nf]);
                        }
                }
                if (vc) {
                    #pragma unroll
                    for (int mf = 0; mf < MF; ++mf)
                        #pragma unroll
                        for (int nf = 0; nf < NF; ++nf) {
                            mma_f16(acc[1][mf][nf], ac[mf], bh[nf]);
                            mma_f16(acc[1][mf][nf], ac[mf], bl[nf]);
                        }
                }
                // carry: A[y+dy] becomes A[y-1+(dy+1)]
                #pragma unroll
                for (int mf = 0; mf < MF; ++mf)
                    #pragma unroll
                    for (int q = 0; q < 4; ++q) ap[mf][q] = ac[mf][q];
                vp = vc;
            }
        }

        #pragma unroll
        for (int r = 0; r < 2; ++r) {
            const int yo = y + r;
            #pragma unroll
            for (int mf = 0; mf < MF; ++mf) {
                const int x = x0 + wm * (MF * 16) + mf * 16 + g;
                #pragma unroll
                for (int nf = 0; nf < NF; ++nf) {
                    const int co = wn * (NF * 8) + nf * 8 + tig * 2;
                    const float v0 = acc[r][mf][nf][0], v1 = acc[r][mf][nf][1];
                    const float v2 = acc[r][mf][nf][2], v3 = acc[r][mf][nf][3];
                    if (OUTH2) {
                        const int cp = co >> 1;
                        uint32_t* p = (uint32_t*)outv +
                            (((size_t)b * (CO / 2) + cp) * H + yo) * W + x;
                        p[0] = packh2(v0, v1);
                        p[8] = packh2(v2, v3);
                    } else {
                        const size_t base =
                            (((size_t)b * CO + co) * H + yo) * W + x;
                        float* p0 = (float*)outv + base;
                        float* p1 = p0 + (size_t)H * W;
                        p0[0] = v0; p1[0] = v1; p0[8] = v2; p1[8] = v3;
                    }
                    if (STATS) {
                        sacc[nf][0] += v0 + v2;
                        sacc[nf][1] += v1 + v3;
                        qacc[nf][0] = fmaf(v0, v0, fmaf(v2, v2, qacc[nf][0]));
                        qacc[nf][1] = fmaf(v1, v1, fmaf(v3, v3, qacc[nf][1]));
                    }
                }
            }
        }
        if (s3) stage_store(s32, y + 3, tid, pf0);
        if (s4) stage_store(s32, y + 4, tid, pf1);
        __syncthreads();
    }

    if (STATS) {
        #pragma unroll
        for (int nf = 0; nf < NF; ++nf)
            #pragma unroll
            for (int j = 0; j < 2; ++j) {
                float s = sacc[nf][j], q = qacc[nf][j];
                #pragma unroll
                for (int o = 4; o < 32; o <<= 1) {
                    s += __shfl_xor_sync(0xffffffffu, s, o);
                    q += __shfl_xor_sync(0xffffffffu, q, o);
                }
                if (g == 0) {
                    const int c = wn * (NF * 8) + nf * 8 + tig * 2 + j;
                    atomicAdd(&sstats[c], s);
                    atomicAdd(&sstats[COUT + c], q);
                }
            }
        __syncthreads();
        if (tid < 128) atomicAdd(&g_stats[tid], sstats[tid]);
    }
}

// ---- scalar tiled conv (conv1), __half2 ci-pair plane output ---------------
template <int CI, int CO, int TH, int TW>
__global__ void __launch_bounds__(256, 2)
conv3x3_tile(const float* __restrict__ in, const float* __restrict__ wgt,
             uint32_t* __restrict__ out) {
    constexpr int NTT = 256, NPX = TH * TW / 8, NCG = CO / 8;
    static_assert(NPX * NCG == NTT, "shape");
    constexpr int IH = TH + 2, IW = TW + 2, RS = (IW + 3) & ~3;
    extern __shared__ float fsm[];
    float* s_in = fsm;
    float* s_w  = fsm + CI * IH * RS;

    const int tid = threadIdx.x;
    int bid = blockIdx.x;
    const int tx = bid % (W / TW); bid /= (W / TW);
    const int ty = bid % (H / TH); bid /= (H / TH);
    const int b = bid;

    for (int i = tid; i < CI * 9 * CO; i += NTT) {
        const int k = i / CO, co = i - k * CO, ci = k / 9, t = k - ci * 9;
        s_w[i] = wgt[(co * CI + ci) * 9 + t];
    }
    const float* inb = in + (size_t)b * CI * H * W;
    const int gy0 = ty * TH - 1, gx0 = tx * TW - 1;
    for (int i = tid; i < CI * IH * IW; i += NTT) {
        const int ci = i / (IH * IW);
        int r = i - ci * IH * IW;
        const int y = r / IW, x = r - y * IW;
        const int gy = gy0 + y, gx = gx0 + x;
        float v = 0.f;
        if (gy >= 0 && gy < H && gx >= 0 && gx < W)
            v = inb[(ci * H + gy) * W + gx];
        s_in[(ci * IH + y) * RS + x] = v;
    }
    __syncthreads();

    const int px = tid % NPX, cg = tid / NPX;
    const int py = px / (TW / 8), x0 = (px - py * (TW / 8)) * 8, co0 = cg * 8;
    float acc[8][8];
    #pragma unroll
    for (int i = 0; i < 8; ++i)
        #pragma unroll
        for (int j = 0; j < 8; ++j) acc[i][j] = 0.f;

    #pragma unroll 1
    for (int ci = 0; ci < CI; ++ci)
        #pragma unroll
        for (int dy = 0; dy < 3; ++dy) {
            const float* rp = &s_in[(ci * IH + py + dy) * RS + x0];
            float rr[10];
            const float4 a0 = *reinterpret_cast<const float4*>(rp);
            const float4 a1 = *reinterpret_cast<const float4*>(rp + 4);
            const float2 a2 = *reinterpret_cast<const float2*>(rp + 8);
            rr[0]=a0.x; rr[1]=a0.y; rr[2]=a0.z; rr[3]=a0.w;
            rr[4]=a1.x; rr[5]=a1.y; rr[6]=a1.z; rr[7]=a1.w;
            rr[8]=a2.x; rr[9]=a2.y;
            #pragma unroll
            for (int dx = 0; dx < 3; ++dx) {
                const float* wp = &s_w[(ci * 9 + dy * 3 + dx) * CO + co0];
                const float4 w0 = *reinterpret_cast<const float4*>(wp);
                const float4 w1 = *reinterpret_cast<const float4*>(wp + 4);
                const float wv[8] = {w0.x, w0.y, w0.z, w0.w, w1.x, w1.y, w1.z, w1.w};
                #pragma unroll
                for (int co = 0; co < 8; ++co)
                    #pragma unroll
                    for (int p = 0; p < 8; ++p)
                        acc[co][p] = fmaf(wv[co], rr[p + dx], acc[co][p]);
            }
        }
    const int oy = ty * TH + py, ox = tx * TW + x0;
    #pragma unroll
    for (int j = 0; j < 4; ++j) {
        uint32_t* op = out +
            (((size_t)b * (CO / 2) + (co0 >> 1) + j) * H + oy) * W + ox;
        uint4 u0, u1;
        u0.x = packh2(acc[2*j][0], acc[2*j+1][0]);
        u0.y = packh2(acc[2*j][1], acc[2*j+1][1]);
        u0.z = packh2(acc[2*j][2], acc[2*j+1][2]);
        u0.w = packh2(acc[2*j][3], acc[2*j+1][3]);
        u1.x = packh2(acc[2*j][4], acc[2*j+1][4]);
        u1.y = packh2(acc[2*j][5], acc[2*j+1][5]);
        u1.z = packh2(acc[2*j][6], acc[2*j+1][6]);
        u1.w = packh2(acc[2*j][7], acc[2*j+1][7]);
        *reinterpret_cast<uint4*>(op)     = u0;
        *reinterpret_cast<uint4*>(op + 4) = u1;
    }
}

__global__ void zero_stats_kernel() {
    if (threadIdx.x < 2 * COUT) g_stats[threadIdx.x] = 0.f;
}
__global__ void bn_finalize_kernel(const float* __restrict__ gamma,
                                   const float* __restrict__ beta) {
    const int c = threadIdx.x;
    if (c >= COUT) return;
    const float n = (float)B * H * W;
    const float mean = g_stats[c] / n;
    const float var  = g_stats[COUT + c] / n - mean * mean;
    const float sc   = gamma[c] * rsqrtf(var + BN_EPS);
    g_scale[c] = sc;
    g_shift[c] = beta[c] - mean * sc;
}
__global__ void bn_apply_kernel(float* __restrict__ out) {
    const int idx = blockIdx.x * blockDim.x + threadIdx.x;
    const int c = (idx >> 14) & (COUT - 1);
    const float sc = g_scale[c], sh = g_shift[c];
    float4 v = reinterpret_cast<float4*>(out)[idx];
    v.x = fmaf(v.x, sc, sh); v.y = fmaf(v.y, sc, sh);
    v.z = fmaf(v.z, sc, sh); v.w = fmaf(v.w, sc, sh);
    reinterpret_cast<float4*>(out)[idx] = v;
}

extern "C" void kernel_launch(void* const* d_in, const int* in_sizes, int n_in,
                              void* d_out, int out_size) {
    (void)in_sizes; (void)n_in; (void)out_size;
    const float* x     = (const float*)d_in[0];
    const float* w1    = (const float*)d_in[1];
    const float* w2    = (const float*)d_in[2];
    const float* w3    = (const float*)d_in[3];
    const float* gamma = (const float*)d_in[4];
    const float* beta  = (const float*)d_in[5];
    float* out = (float*)d_out;

    uint32_t *h1, *h2;
    cudaGetSymbolAddress((void**)&h1, g_h1);
    cudaGetSymbolAddress((void**)&h2, g_h2);

    auto* k1 = conv3x3_tile<CIN0, CMID, 32, 32>;
    auto* k2 = conv_mma<16, 4, 2, 2, 1, false, true>;   // h1 -> half2 h2
    auto* k3 = conv_mma<64, 4, 2, 2, 4, true,  false>;  // h2 -> fp32 out

    constexpr int SM1 = (CIN0 * 34 * 36 + CIN0 * 9 * CMID) * 4;
    constexpr int SM2 = BBASE + 3 * (2 * 16 * 112) + 512;   // 61,952
    constexpr int SM3 = BBASE + 3 * (2 * 64 * 112) + 512;   // 94,208

    cudaFuncSetAttribute(k1, cudaFuncAttributeMaxDynamicSharedMemorySize, SM1);
    cudaFuncSetAttribute(k2, cudaFuncAttributeMaxDynamicSharedMemorySize, SM2);
    cudaFuncSetAttribute(k3, cudaFuncAttributeMaxDynamicSharedMemorySize, SM3);

    zero_stats_kernel<<<1, 128>>>();
    k1<<<B * (H / 32) * (W / 32), 256, SM1>>>(x, w1, h1);
    k2<<<B * 32 * 2, NT, SM2>>>(h1, w2, h2);
    k3<<<B * 32 * 2, NT, SM3>>>(h2, w3, out);
    bn_finalize_kernel<<<1, 64>>>(gamma, beta);
    bn_apply_kernel<<<(B * COUT * H * W / 4) / 256, 256>>>(out);
}

// round 16
// speedup vs baseline: 1.1808x; 1.1808x over previous
#include <cuda_runtime.h>
#include <cuda_fp16.h>
#include <cstdint>

static constexpr int B = 16, H = 256, W = 256;
static constexpr int CIN0 = 3, CMID = 16, COUT = 64;
static constexpr float BN_EPS = 1e-5f;

// h1/h2: fp16, stored as __half2 ci-pair planes: [b][ci/2][y][x] (uint32)
__device__ uint32_t g_h1[(size_t)B * (CMID / 2) * H * W];
__device__ uint32_t g_h2[(size_t)B * (CMID / 2) * H * W];
__device__ float g_stats[2 * COUT];
__device__ float g_scale[COUT];
__device__ float g_shift[COUT];

// ---- helpers ---------------------------------------------------------------
__device__ __forceinline__ uint32_t smem_u32(const void* p) {
    uint32_t a;
    asm("{ .reg .u64 t; cvta.to.shared.u64 t, %1; cvt.u32.u64 %0, t; }"
        : "=r"(a) : "l"(p));
    return a;
}
__device__ __forceinline__ void sts64(uint32_t a, uint32_t x, uint32_t y) {
    asm volatile("st.shared.v2.u32 [%0], {%1,%2};" :: "r"(a), "r"(x), "r"(y));
}
__device__ __forceinline__ void sts16(uint32_t a, uint16_t v) {
    asm volatile("st.shared.u16 [%0], %1;" :: "r"(a), "h"(v));
}
__device__ __forceinline__ uint32_t lds32(uint32_t a) {
    uint32_t v;
    asm volatile("ld.shared.b32 %0, [%1];" : "=r"(v) : "r"(a));
    return v;
}
__device__ __forceinline__ uint32_t packh2(float lo, float hi) {
    const __half h0 = __float2half_rn(lo), h1 = __float2half_rn(hi);
    return ((uint32_t)__half_as_ushort(h1) << 16) |
           (uint32_t)__half_as_ushort(h0);
}
// baseline-PTX fp16 tensor-core mma (sm_80+)
__device__ __forceinline__ void mma_f16(float d[4], const uint32_t a[4],
                                        const uint32_t b[2]) {
    asm volatile(
        "mma.sync.aligned.m16n8k16.row.col.f32.f16.f16.f32 "
        "{%0,%1,%2,%3},{%4,%5,%6,%7},{%8,%9},{%0,%1,%2,%3};"
        : "+f"(d[0]), "+f"(d[1]), "+f"(d[2]), "+f"(d[3])
        : "r"(a[0]), "r"(a[1]), "r"(a[2]), "r"(a[3]), "r"(b[0]), "r"(b[1]));
}

// ---- tensor-core 3x3 conv (16 in-ch), fp16 acts ----------------------------
// A per input row UNSHIFTED: [130 xl][16 ci fp16], stride 48 B (conflict-free
// banks: 12g+tig distinct mod 32); dx shift = +ks*48 address offset at
// fragment load. Ring of 4 rows. B per dy: [CO][48 fp16], stride 112 B.
// WSPLIT: weights split hi+lo (2 MMAs/step, exact weights); else plain fp16
// weights (1 MMA/step).
static constexpr int AXS   = 48;
static constexpr int ASLOT = 132 * AXS;         // 6336 per row
static constexpr int BBASE = 4 * ASLOT;         // 25344
static constexpr int NY    = 8;
static constexpr int NT    = 256;
static constexpr int NITEM = 520;               // 130 xl * 4 ci-groups

__device__ __forceinline__ void stage_load(const uint32_t* in, int b, int yin,
                                           int x0, int tid, uint32_t v[3][2]) {
    #pragma unroll
    for (int j = 0; j < 3; ++j) {
        v[j][0] = v[j][1] = 0;
        const int it = tid + j * NT;
        if (it >= NITEM) continue;
        const int xl = it >> 2, cig = it & 3, xin = x0 - 1 + xl;
        if (xin >= 0 && xin < W) {
            const uint32_t* p =
                in + (((size_t)b * 8 + cig * 2) * H + yin) * W + xin;
            v[j][0] = p[0];
            v[j][1] = p[(size_t)H * W];
        }
    }
}
__device__ __forceinline__ void stage_store(uint32_t s32, int yin, int tid,
                                            const uint32_t v[3][2]) {
    const uint32_t Ah = s32 + (uint32_t)(yin & 3) * ASLOT;
    #pragma unroll
    for (int j = 0; j < 3; ++j) {
        const int it = tid + j * NT;
        if (it >= NITEM) continue;
        const int xl = it >> 2, cig = it & 3;
        sts64(Ah + (uint32_t)(xl * AXS + cig * 8), v[j][0], v[j][1]);
    }
}

// Warp grid WM x WN, per-warp fragments MF x NF.
// WM*MF*16 == 128, WN*NF*8 == CO, WM*WN == 8 (256 threads).
template <int CO, int WM, int WN, int MF, int NF, bool STATS, bool OUTH2,
          bool WSPLIT>
__global__ void __launch_bounds__(NT, 2)
conv_mma(const uint32_t* __restrict__ in, const float* __restrict__ wgt,
         void* __restrict__ outv) {
    static_assert(WM * MF * 16 == 128 && WN * NF * 8 == CO && WM * WN == 8, "");
    constexpr int BLO  = CO * 112;
    constexpr int BDY  = (WSPLIT ? 2 : 1) * BLO;
    constexpr int SOFF = BBASE + 3 * BDY;

    extern __shared__ char sm[];
    const uint32_t s32 = smem_u32(sm);
    float* sstats = (float*)(sm + SOFF);
    const int tid = threadIdx.x, wid = tid >> 5, lid = tid & 31;
    const int g = lid >> 2, tig = lid & 3;
    int bid = blockIdx.x;
    const int xs = bid & 1, ys = (bid >> 1) & 31, b = bid >> 6;
    const int x0 = xs * 128, y0 = ys * NY;

    if (STATS && tid < 128) sstats[tid] = 0.f;
    for (int i = tid; i < CO * CMID * 9; i += NT) {   // weights -> B tiles
        const int dx = i % 3; int t = i / 3;
        const int dy = t % 3; t /= 3;
        const int ci = t & 15, co = t >> 4;
        const float v = wgt[((co * CMID + ci) * 3 + dy) * 3 + dx];
        const __half h = __float2half_rn(v);
        const uint32_t a = s32 + BBASE + dy * BDY + co * 112 + (dx * 16 + ci) * 2;
        sts16(a, (uint16_t)__half_as_ushort(h));
        if (WSPLIT) {
            const __half l = __float2half_rn(v - __half2float(h));
            sts16(a + BLO, (uint16_t)__half_as_ushort(l));
        }
    }
    {   // prologue: rows y0-1, y0, y0+1
        uint32_t pv[3][2];
        if (y0 > 0) {
            stage_load(in, b, y0 - 1, x0, tid, pv);
            stage_store(s32, y0 - 1, tid, pv);
        }
        stage_load(in, b, y0, x0, tid, pv);
        stage_store(s32, y0, tid, pv);
        stage_load(in, b, y0 + 1, x0, tid, pv);
        stage_store(s32, y0 + 1, tid, pv);
    }
    __syncthreads();

    const int wm = wid % WM, wn = wid / WM;
    float sacc[NF][2] = {}, qacc[NF][2] = {};

    for (int i = 0; i < NY; ++i) {
        const int y = y0 + i;
        const bool have = (y + 2 < H);
        uint32_t pf[3][2];
        if (have) stage_load(in, b, y + 2, x0, tid, pf);  // LDG early

        float acc[MF][NF][4];
        #pragma unroll
        for (int mf = 0; mf < MF; ++mf)
            #pragma unroll
            for (int nf = 0; nf < NF; ++nf)
                #pragma unroll
                for (int r = 0; r < 4; ++r) acc[mf][nf][r] = 0.f;

        #pragma unroll
        for (int dy = 0; dy < 3; ++dy) {
            const int yin = y - 1 + dy;
            if (yin < 0 || yin >= H) continue;
            const uint32_t A0 = s32 + (uint32_t)(yin & 3) * ASLOT;
            const uint32_t B0 = s32 + BBASE + dy * BDY;
            #pragma unroll
            for (int ks = 0; ks < 3; ++ks) {
                uint32_t a[MF][4], bh[NF][2], bl[NF][2];
                #pragma unroll
                for (int mf = 0; mf < MF; ++mf) {
                    // unshifted A: xl = px + ks
                    const uint32_t r0 = A0 +
                        (uint32_t)((wm * (MF * 16) + mf * 16 + g + ks) * AXS +
                                   tig * 4);
                    const uint32_t r1 = r0 + 8 * AXS;
                    a[mf][0] = lds32(r0);      a[mf][1] = lds32(r1);
                    a[mf][2] = lds32(r0 + 16); a[mf][3] = lds32(r1 + 16);
                }
                #pragma unroll
                for (int nf = 0; nf < NF; ++nf) {
                    const uint32_t c0 = B0 +
                        (uint32_t)((wn * (NF * 8) + nf * 8 + g) * 112 +
                                   ks * 32 + tig * 4);
                    bh[nf][0] = lds32(c0);
                    bh[nf][1] = lds32(c0 + 16);
                    if (WSPLIT) {
                        bl[nf][0] = lds32(c0 + BLO);
                        bl[nf][1] = lds32(c0 + BLO + 16);
                    }
                }
                #pragma unroll
                for (int mf = 0; mf < MF; ++mf)
                    #pragma unroll
                    for (int nf = 0; nf < NF; ++nf) {
                        mma_f16(acc[mf][nf], a[mf], bh[nf]);
                        if (WSPLIT) mma_f16(acc[mf][nf], a[mf], bl[nf]);
                    }
            }
        }

        #pragma unroll
        for (int mf = 0; mf < MF; ++mf) {
            const int x = x0 + wm * (MF * 16) + mf * 16 + g;
            #pragma unroll
            for (int nf = 0; nf < NF; ++nf) {
                const int co = wn * (NF * 8) + nf * 8 + tig * 2;
                const float v0 = acc[mf][nf][0], v1 = acc[mf][nf][1];
                const float v2 = acc[mf][nf][2], v3 = acc[mf][nf][3];
                if (OUTH2) {
                    const int cp = co >> 1;
                    uint32_t* p = (uint32_t*)outv +
                        (((size_t)b * (CO / 2) + cp) * H + y) * W + x;
                    p[0] = packh2(v0, v1);
                    p[8] = packh2(v2, v3);
                } else {
                    const size_t base = (((size_t)b * CO + co) * H + y) * W + x;
                    float* p0 = (float*)outv + base;
                    float* p1 = p0 + (size_t)H * W;
                    p0[0] = v0; p1[0] = v1; p0[8] = v2; p1[8] = v3;
                }
                if (STATS) {
                    sacc[nf][0] += v0 + v2;
                    sacc[nf][1] += v1 + v3;
                    qacc[nf][0] = fmaf(v0, v0, fmaf(v2, v2, qacc[nf][0]));
                    qacc[nf][1] = fmaf(v1, v1, fmaf(v3, v3, qacc[nf][1]));
                }
            }
        }
        if (have) stage_store(s32, y + 2, tid, pf);  // slot (y+2)&3 disjoint
        __syncthreads();
    }

    if (STATS) {
        #pragma unroll
        for (int nf = 0; nf < NF; ++nf)
            #pragma unroll
            for (int j = 0; j < 2; ++j) {
                float s = sacc[nf][j], q = qacc[nf][j];
                #pragma unroll
                for (int o = 4; o < 32; o <<= 1) {
                    s += __shfl_xor_sync(0xffffffffu, s, o);
                    q += __shfl_xor_sync(0xffffffffu, q, o);
                }
                if (g == 0) {
                    const int c = wn * (NF * 8) + nf * 8 + tig * 2 + j;
                    atomicAdd(&sstats[c], s);
                    atomicAdd(&sstats[COUT + c], q);
                }
            }
        __syncthreads();
        if (tid < 128) atomicAdd(&g_stats[tid], sstats[tid]);
    }
}

// ---- scalar tiled conv (conv1), __half2 ci-pair plane output ---------------
template <int CI, int CO, int TH, int TW>
__global__ void __launch_bounds__(256, 2)
conv3x3_tile(const float* __restrict__ in, const float* __restrict__ wgt,
             uint32_t* __restrict__ out) {
    constexpr int NTT = 256, NPX = TH * TW / 8, NCG = CO / 8;
    static_assert(NPX * NCG == NTT, "shape");
    constexpr int IH = TH + 2, IW = TW + 2, RS = (IW + 3) & ~3;
    extern __shared__ float fsm[];
    float* s_in = fsm;
    float* s_w  = fsm + CI * IH * RS;

    const int tid = threadIdx.x;
    int bid = blockIdx.x;
    const int tx = bid % (W / TW); bid /= (W / TW);
    const int ty = bid % (H / TH); bid /= (H / TH);
    const int b = bid;

    for (int i = tid; i < CI * 9 * CO; i += NTT) {
        const int k = i / CO, co = i - k * CO, ci = k / 9, t = k - ci * 9;
        s_w[i] = wgt[(co * CI + ci) * 9 + t];
    }
    const float* inb = in + (size_t)b * CI * H * W;
    const int gy0 = ty * TH - 1, gx0 = tx * TW - 1;
    for (int i = tid; i < CI * IH * IW; i += NTT) {
        const int ci = i / (IH * IW);
        int r = i - ci * IH * IW;
        const int y = r / IW, x = r - y * IW;
        const int gy = gy0 + y, gx = gx0 + x;
        float v = 0.f;
        if (gy >= 0 && gy < H && gx >= 0 && gx < W)
            v = inb[(ci * H + gy) * W + gx];
        s_in[(ci * IH + y) * RS + x] = v;
    }
    __syncthreads();

    const int px = tid % NPX, cg = tid / NPX;
    const int py = px / (TW / 8), x0 = (px - py * (TW / 8)) * 8, co0 = cg * 8;
    float acc[8][8];
    #pragma unroll
    for (int i = 0; i < 8; ++i)
        #pragma unroll
        for (int j = 0; j < 8; ++j) acc[i][j] = 0.f;

    #pragma unroll 1
    for (int ci = 0; ci < CI; ++ci)
        #pragma unroll
        for (int dy = 0; dy < 3; ++dy) {
            const float* rp = &s_in[(ci * IH + py + dy) * RS + x0];
            float rr[10];
            const float4 a0 = *reinterpret_cast<const float4*>(rp);
            const float4 a1 = *reinterpret_cast<const float4*>(rp + 4);
            const float2 a2 = *reinterpret_cast<const float2*>(rp + 8);
            rr[0]=a0.x; rr[1]=a0.y; rr[2]=a0.z; rr[3]=a0.w;
            rr[4]=a1.x; rr[5]=a1.y; rr[6]=a1.z; rr[7]=a1.w;
            rr[8]=a2.x; rr[9]=a2.y;
            #pragma unroll
            for (int dx = 0; dx < 3; ++dx) {
                const float* wp = &s_w[(ci * 9 + dy * 3 + dx) * CO + co0];
                const float4 w0 = *reinterpret_cast<const float4*>(wp);
                const float4 w1 = *reinterpret_cast<const float4*>(wp + 4);
                const float wv[8] = {w0.x, w0.y, w0.z, w0.w, w1.x, w1.y, w1.z, w1.w};
                #pragma unroll
                for (int co = 0; co < 8; ++co)
                    #pragma unroll
                    for (int p = 0; p < 8; ++p)
                        acc[co][p] = fmaf(wv[co], rr[p + dx], acc[co][p]);
            }
        }
    const int oy = ty * TH + py, ox = tx * TW + x0;
    #pragma unroll
    for (int j = 0; j < 4; ++j) {
        uint32_t* op = out +
            (((size_t)b * (CO / 2) + (co0 >> 1) + j) * H + oy) * W + ox;
        uint4 u0, u1;
        u0.x = packh2(acc[2*j][0], acc[2*j+1][0]);
        u0.y = packh2(acc[2*j][1], acc[2*j+1][1]);
        u0.z = packh2(acc[2*j][2], acc[2*j+1][2]);
        u0.w = packh2(acc[2*j][3], acc[2*j+1][3]);
        u1.x = packh2(acc[2*j][4], acc[2*j+1][4]);
        u1.y = packh2(acc[2*j][5], acc[2*j+1][5]);
        u1.z = packh2(acc[2*j][6], acc[2*j+1][6]);
        u1.w = packh2(acc[2*j][7], acc[2*j+1][7]);
        *reinterpret_cast<uint4*>(op)     = u0;
        *reinterpret_cast<uint4*>(op + 4) = u1;
    }
}

__global__ void zero_stats_kernel() {
    if (threadIdx.x < 2 * COUT) g_stats[threadIdx.x] = 0.f;
}
__global__ void bn_finalize_kernel(const float* __restrict__ gamma,
                                   const float* __restrict__ beta) {
    const int c = threadIdx.x;
    if (c >= COUT) return;
    const float n = (float)B * H * W;
    const float mean = g_stats[c] / n;
    const float var  = g_stats[COUT + c] / n - mean * mean;
    const float sc   = gamma[c] * rsqrtf(var + BN_EPS);
    g_scale[c] = sc;
    g_shift[c] = beta[c] - mean * sc;
}
__global__ void bn_apply_kernel(float* __restrict__ out) {
    const int idx = blockIdx.x * blockDim.x + threadIdx.x;
    const int c = (idx >> 14) & (COUT - 1);
    const float sc = g_scale[c], sh = g_shift[c];
    float4 v = reinterpret_cast<float4*>(out)[idx];
    v.x = fmaf(v.x, sc, sh); v.y = fmaf(v.y, sc, sh);
    v.z = fmaf(v.z, sc, sh); v.w = fmaf(v.w, sc, sh);
    reinterpret_cast<float4*>(out)[idx] = v;
}

extern "C" void kernel_launch(void* const* d_in, const int* in_sizes, int n_in,
                              void* d_out, int out_size) {
    (void)in_sizes; (void)n_in; (void)out_size;
    const float* x     = (const float*)d_in[0];
    const float* w1    = (const float*)d_in[1];
    const float* w2    = (const float*)d_in[2];
    const float* w3    = (const float*)d_in[3];
    const float* gamma = (const float*)d_in[4];
    const float* beta  = (const float*)d_in[5];
    float* out = (float*)d_out;

    uint32_t *h1, *h2;
    cudaGetSymbolAddress((void**)&h1, g_h1);
    cudaGetSymbolAddress((void**)&h2, g_h2);

    auto* k1 = conv3x3_tile<CIN0, CMID, 32, 32>;
    auto* k2 = conv_mma<16, 8, 1, 1, 2, false, true,  false>;  // h1 -> h2
    auto* k3 = conv_mma<64, 4, 2, 2, 4, true,  false, false>;  // h2 -> out

    constexpr int SM1 = (CIN0 * 34 * 36 + CIN0 * 9 * CMID) * 4;
    constexpr int SM2 = BBASE + 3 * (16 * 112) + 512;   // 31,232
    constexpr int SM3 = BBASE + 3 * (64 * 112) + 512;   // 47,360

    cudaFuncSetAttribute(k1, cudaFuncAttributeMaxDynamicSharedMemorySize, SM1);
    cudaFuncSetAttribute(k2, cudaFuncAttributeMaxDynamicSharedMemorySize, SM2);
    cudaFuncSetAttribute(k3, cudaFuncAttributeMaxDynamicSharedMemorySize, SM3);

    zero_stats_kernel<<<1, 128>>>();
    k1<<<B * (H / 32) * (W / 32), 256, SM1>>>(x, w1, h1);
    k2<<<B * 32 * 2, NT, SM2>>>(h1, w2, h2);
    k3<<<B * 32 * 2, NT, SM3>>>(h2, w3, out);
    bn_finalize_kernel<<<1, 64>>>(gamma, beta);
    bn_apply_kernel<<<(B * COUT * H * W / 4) / 256, 256>>>(out);
}

// round 17
// speedup vs baseline: 1.3277x; 1.1244x over previous
#include <cuda_runtime.h>
#include <cuda_fp16.h>
#include <cstdint>

static constexpr int B = 16, H = 256, W = 256;
static constexpr int CIN0 = 3, CMID = 16, COUT = 64;
static constexpr float BN_EPS = 1e-5f;

// h1/h2: fp16 __half2 ci-pair planes [b][ci/2][y][x]; h3: pre-BN conv3 output
// as fp16 co-pair planes [b][co/2][y][x]
__device__ uint32_t g_h1[(size_t)B * (CMID / 2) * H * W];
__device__ uint32_t g_h2[(size_t)B * (CMID / 2) * H * W];
__device__ uint32_t g_h3[(size_t)B * (COUT / 2) * H * W];   // 128 MB
__device__ float g_stats[2 * COUT];
__device__ float g_scale[COUT];
__device__ float g_shift[COUT];

// ---- helpers ---------------------------------------------------------------
__device__ __forceinline__ uint32_t smem_u32(const void* p) {
    uint32_t a;
    asm("{ .reg .u64 t; cvta.to.shared.u64 t, %1; cvt.u32.u64 %0, t; }"
        : "=r"(a) : "l"(p));
    return a;
}
__device__ __forceinline__ void sts64(uint32_t a, uint32_t x, uint32_t y) {
    asm volatile("st.shared.v2.u32 [%0], {%1,%2};" :: "r"(a), "r"(x), "r"(y));
}
__device__ __forceinline__ void sts16(uint32_t a, uint16_t v) {
    asm volatile("st.shared.u16 [%0], %1;" :: "r"(a), "h"(v));
}
__device__ __forceinline__ uint32_t lds32(uint32_t a) {
    uint32_t v;
    asm volatile("ld.shared.b32 %0, [%1];" : "=r"(v) : "r"(a));
    return v;
}
__device__ __forceinline__ uint32_t packh2(float lo, float hi) {
    const __half h0 = __float2half_rn(lo), h1 = __float2half_rn(hi);
    return ((uint32_t)__half_as_ushort(h1) << 16) |
           (uint32_t)__half_as_ushort(h0);
}
// baseline-PTX fp16 tensor-core mma (sm_80+)
__device__ __forceinline__ void mma_f16(float d[4], const uint32_t a[4],
                                        const uint32_t b[2]) {
    asm volatile(
        "mma.sync.aligned.m16n8k16.row.col.f32.f16.f16.f32 "
        "{%0,%1,%2,%3},{%4,%5,%6,%7},{%8,%9},{%0,%1,%2,%3};"
        : "+f"(d[0]), "+f"(d[1]), "+f"(d[2]), "+f"(d[3])
        : "r"(a[0]), "r"(a[1]), "r"(a[2]), "r"(a[3]), "r"(b[0]), "r"(b[1]));
}

// ---- tensor-core 3x3 conv (16 in-ch), fp16 acts ----------------------------
// A per input row UNSHIFTED: [130 xl][16 ci fp16], stride 48 B (conflict-free
// banks); dx shift = +ks*48 address offset at fragment load. Ring of 4 rows.
// B per dy: [CO][48 fp16], stride 112 B. One MMA per (dy,ks).
static constexpr int AXS   = 48;
static constexpr int ASLOT = 132 * AXS;         // 6336 per row
static constexpr int BBASE = 4 * ASLOT;         // 25344
static constexpr int NY    = 8;
static constexpr int NT    = 256;
static constexpr int NITEM = 520;               // 130 xl * 4 ci-groups

__device__ __forceinline__ void stage_load(const uint32_t* in, int b, int yin,
                                           int x0, int tid, uint32_t v[3][2]) {
    #pragma unroll
    for (int j = 0; j < 3; ++j) {
        v[j][0] = v[j][1] = 0;
        const int it = tid + j * NT;
        if (it >= NITEM) continue;
        const int xl = it >> 2, cig = it & 3, xin = x0 - 1 + xl;
        if (xin >= 0 && xin < W) {
            const uint32_t* p =
                in + (((size_t)b * 8 + cig * 2) * H + yin) * W + xin;
            v[j][0] = p[0];
            v[j][1] = p[(size_t)H * W];
        }
    }
}
__device__ __forceinline__ void stage_store(uint32_t s32, int yin, int tid,
                                            const uint32_t v[3][2]) {
    const uint32_t Ah = s32 + (uint32_t)(yin & 3) * ASLOT;
    #pragma unroll
    for (int j = 0; j < 3; ++j) {
        const int it = tid + j * NT;
        if (it >= NITEM) continue;
        const int xl = it >> 2, cig = it & 3;
        sts64(Ah + (uint32_t)(xl * AXS + cig * 8), v[j][0], v[j][1]);
    }
}

// Warp grid WM x WN, per-warp fragments MF x NF.
// WM*MF*16 == 128, WN*NF*8 == CO, WM*WN == 8 (256 threads).
// Output: __half2 co-pair planes [b][co/2][y][x].
template <int CO, int WM, int WN, int MF, int NF, bool STATS>
__global__ void __launch_bounds__(NT, 2)
conv_mma(const uint32_t* __restrict__ in, const float* __restrict__ wgt,
         uint32_t* __restrict__ outp) {
    static_assert(WM * MF * 16 == 128 && WN * NF * 8 == CO && WM * WN == 8, "");
    constexpr int BDY  = CO * 112;
    constexpr int SOFF = BBASE + 3 * BDY;

    extern __shared__ char sm[];
    const uint32_t s32 = smem_u32(sm);
    float* sstats = (float*)(sm + SOFF);
    const int tid = threadIdx.x, wid = tid >> 5, lid = tid & 31;
    const int g = lid >> 2, tig = lid & 3;
    int bid = blockIdx.x;
    const int xs = bid & 1, ys = (bid >> 1) & 31, b = bid >> 6;
    const int x0 = xs * 128, y0 = ys * NY;

    if (STATS && tid < 128) sstats[tid] = 0.f;
    for (int i = tid; i < CO * CMID * 9; i += NT) {   // weights -> B tiles
        const int dx = i % 3; int t = i / 3;
        const int dy = t % 3; t /= 3;
        const int ci = t & 15, co = t >> 4;
        const float v = wgt[((co * CMID + ci) * 3 + dy) * 3 + dx];
        const uint32_t a = s32 + BBASE + dy * BDY + co * 112 + (dx * 16 + ci) * 2;
        sts16(a, (uint16_t)__half_as_ushort(__float2half_rn(v)));
    }
    {   // prologue: rows y0-1, y0, y0+1
        uint32_t pv[3][2];
        if (y0 > 0) {
            stage_load(in, b, y0 - 1, x0, tid, pv);
            stage_store(s32, y0 - 1, tid, pv);
        }
        stage_load(in, b, y0, x0, tid, pv);
        stage_store(s32, y0, tid, pv);
        stage_load(in, b, y0 + 1, x0, tid, pv);
        stage_store(s32, y0 + 1, tid, pv);
    }
    __syncthreads();

    const int wm = wid % WM, wn = wid / WM;
    float sacc[NF][2] = {}, qacc[NF][2] = {};

    for (int i = 0; i < NY; ++i) {
        const int y = y0 + i;
        const bool have = (y + 2 < H);
        uint32_t pf[3][2];
        if (have) stage_load(in, b, y + 2, x0, tid, pf);  // LDG early

        float acc[MF][NF][4];
        #pragma unroll
        for (int mf = 0; mf < MF; ++mf)
            #pragma unroll
            for (int nf = 0; nf < NF; ++nf)
                #pragma unroll
                for (int r = 0; r < 4; ++r) acc[mf][nf][r] = 0.f;

        #pragma unroll
        for (int dy = 0; dy < 3; ++dy) {
            const int yin = y - 1 + dy;
            if (yin < 0 || yin >= H) continue;
            const uint32_t A0 = s32 + (uint32_t)(yin & 3) * ASLOT;
            const uint32_t B0 = s32 + BBASE + dy * BDY;
            #pragma unroll
            for (int ks = 0; ks < 3; ++ks) {
                uint32_t a[MF][4], bh[NF][2];
                #pragma unroll
                for (int mf = 0; mf < MF; ++mf) {
                    const uint32_t r0 = A0 +
                        (uint32_t)((wm * (MF * 16) + mf * 16 + g + ks) * AXS +
                                   tig * 4);
                    const uint32_t r1 = r0 + 8 * AXS;
                    a[mf][0] = lds32(r0);      a[mf][1] = lds32(r1);
                    a[mf][2] = lds32(r0 + 16); a[mf][3] = lds32(r1 + 16);
                }
                #pragma unroll
                for (int nf = 0; nf < NF; ++nf) {
                    const uint32_t c0 = B0 +
                        (uint32_t)((wn * (NF * 8) + nf * 8 + g) * 112 +
                                   ks * 32 + tig * 4);
                    bh[nf][0] = lds32(c0);
                    bh[nf][1] = lds32(c0 + 16);
                }
                #pragma unroll
                for (int mf = 0; mf < MF; ++mf)
                    #pragma unroll
                    for (int nf = 0; nf < NF; ++nf)
                        mma_f16(acc[mf][nf], a[mf], bh[nf]);
            }
        }

        #pragma unroll
        for (int mf = 0; mf < MF; ++mf) {
            const int x = x0 + wm * (MF * 16) + mf * 16 + g;
            #pragma unroll
            for (int nf = 0; nf < NF; ++nf) {
                const int co = wn * (NF * 8) + nf * 8 + tig * 2;
                const float v0 = acc[mf][nf][0], v1 = acc[mf][nf][1];
                const float v2 = acc[mf][nf][2], v3 = acc[mf][nf][3];
                const int cp = co >> 1;
                uint32_t* p = outp +
                    (((size_t)b * (CO / 2) + cp) * H + y) * W + x;
                p[0] = packh2(v0, v1);
                p[8] = packh2(v2, v3);
                if (STATS) {
                    sacc[nf][0] += v0 + v2;
                    sacc[nf][1] += v1 + v3;
                    qacc[nf][0] = fmaf(v0, v0, fmaf(v2, v2, qacc[nf][0]));
                    qacc[nf][1] = fmaf(v1, v1, fmaf(v3, v3, qacc[nf][1]));
                }
            }
        }
        if (have) stage_store(s32, y + 2, tid, pf);  // slot (y+2)&3 disjoint
        __syncthreads();
    }

    if (STATS) {
        #pragma unroll
        for (int nf = 0; nf < NF; ++nf)
            #pragma unroll
            for (int j = 0; j < 2; ++j) {
                float s = sacc[nf][j], q = qacc[nf][j];
                #pragma unroll
                for (int o = 4; o < 32; o <<= 1) {
                    s += __shfl_xor_sync(0xffffffffu, s, o);
                    q += __shfl_xor_sync(0xffffffffu, q, o);
                }
                if (g == 0) {
                    const int c = wn * (NF * 8) + nf * 8 + tig * 2 + j;
                    atomicAdd(&sstats[c], s);
                    atomicAdd(&sstats[COUT + c], q);
                }
            }
        __syncthreads();
        if (tid < 128) atomicAdd(&g_stats[tid], sstats[tid]);
    }
}

// ---- scalar tiled conv (conv1), __half2 ci-pair plane output ---------------
template <int CI, int CO, int TH, int TW>
__global__ void __launch_bounds__(256, 2)
conv3x3_tile(const float* __restrict__ in, const float* __restrict__ wgt,
             uint32_t* __restrict__ out) {
    constexpr int NTT = 256, NPX = TH * TW / 8, NCG = CO / 8;
    static_assert(NPX * NCG == NTT, "shape");
    constexpr int IH = TH + 2, IW = TW + 2, RS = (IW + 3) & ~3;
    extern __shared__ float fsm[];
    float* s_in = fsm;
    float* s_w  = fsm + CI * IH * RS;

    const int tid = threadIdx.x;
    int bid = blockIdx.x;
    const int tx = bid % (W / TW); bid /= (W / TW);
    const int ty = bid % (H / TH); bid /= (H / TH);
    const int b = bid;

    for (int i = tid; i < CI * 9 * CO; i += NTT) {
        const int k = i / CO, co = i - k * CO, ci = k / 9, t = k - ci * 9;
        s_w[i] = wgt[(co * CI + ci) * 9 + t];
    }
    const float* inb = in + (size_t)b * CI * H * W;
    const int gy0 = ty * TH - 1, gx0 = tx * TW - 1;
    for (int i = tid; i < CI * IH * IW; i += NTT) {
        const int ci = i / (IH * IW);
        int r = i - ci * IH * IW;
        const int y = r / IW, x = r - y * IW;
        const int gy = gy0 + y, gx = gx0 + x;
        float v = 0.f;
        if (gy >= 0 && gy < H && gx >= 0 && gx < W)
            v = inb[(ci * H + gy) * W + gx];
        s_in[(ci * IH + y) * RS + x] = v;
    }
    __syncthreads();

    const int px = tid % NPX, cg = tid / NPX;
    const int py = px / (TW / 8), x0 = (px - py * (TW / 8)) * 8, co0 = cg * 8;
    float acc[8][8];
    #pragma unroll
    for (int i = 0; i < 8; ++i)
        #pragma unroll
        for (int j = 0; j < 8; ++j) acc[i][j] = 0.f;

    #pragma unroll 1
    for (int ci = 0; ci < CI; ++ci)
        #pragma unroll
        for (int dy = 0; dy < 3; ++dy) {
            const float* rp = &s_in[(ci * IH + py + dy) * RS + x0];
            float rr[10];
            const float4 a0 = *reinterpret_cast<const float4*>(rp);
            const float4 a1 = *reinterpret_cast<const float4*>(rp + 4);
            const float2 a2 = *reinterpret_cast<const float2*>(rp + 8);
            rr[0]=a0.x; rr[1]=a0.y; rr[2]=a0.z; rr[3]=a0.w;
            rr[4]=a1.x; rr[5]=a1.y; rr[6]=a1.z; rr[7]=a1.w;
            rr[8]=a2.x; rr[9]=a2.y;
            #pragma unroll
            for (int dx = 0; dx < 3; ++dx) {
                const float* wp = &s_w[(ci * 9 + dy * 3 + dx) * CO + co0];
                const float4 w0 = *reinterpret_cast<const float4*>(wp);
                const float4 w1 = *reinterpret_cast<const float4*>(wp + 4);
                const float wv[8] = {w0.x, w0.y, w0.z, w0.w, w1.x, w1.y, w1.z, w1.w};
                #pragma unroll
                for (int co = 0; co < 8; ++co)
                    #pragma unroll
                    for (int p = 0; p < 8; ++p)
                        acc[co][p] = fmaf(wv[co], rr[p + dx], acc[co][p]);
            }
        }
    const int oy = ty * TH + py, ox = tx * TW + x0;
    #pragma unroll
    for (int j = 0; j < 4; ++j) {
        uint32_t* op = out +
            (((size_t)b * (CO / 2) + (co0 >> 1) + j) * H + oy) * W + ox;
        uint4 u0, u1;
        u0.x = packh2(acc[2*j][0], acc[2*j+1][0]);
        u0.y = packh2(acc[2*j][1], acc[2*j+1][1]);
        u0.z = packh2(acc[2*j][2], acc[2*j+1][2]);
        u0.w = packh2(acc[2*j][3], acc[2*j+1][3]);
        u1.x = packh2(acc[2*j][4], acc[2*j+1][4]);
        u1.y = packh2(acc[2*j][5], acc[2*j+1][5]);
        u1.z = packh2(acc[2*j][6], acc[2*j+1][6]);
        u1.w = packh2(acc[2*j][7], acc[2*j+1][7]);
        *reinterpret_cast<uint4*>(op)     = u0;
        *reinterpret_cast<uint4*>(op + 4) = u1;
    }
}

__global__ void zero_stats_kernel() {
    if (threadIdx.x < 2 * COUT) g_stats[threadIdx.x] = 0.f;
}
__global__ void bn_finalize_kernel(const float* __restrict__ gamma,
                                   const float* __restrict__ beta) {
    const int c = threadIdx.x;
    if (c >= COUT) return;
    const float n = (float)B * H * W;
    const float mean = g_stats[c] / n;
    const float var  = g_stats[COUT + c] / n - mean * mean;
    const float sc   = gamma[c] * rsqrtf(var + BN_EPS);
    g_scale[c] = sc;
    g_shift[c] = beta[c] - mean * sc;
}

// Unpack fp16 co-pair planes, apply scale/shift, write fp32 NCHW.
// Each thread handles one uint4 = 4 packed pairs = 8 output values.
// Pair plane cp has 65536 elems -> 16384 uint4; cp = (idx >> 14) & 31.
__global__ void __launch_bounds__(256)
bn_apply_h2_kernel(const uint32_t* __restrict__ h3, float* __restrict__ out) {
    const int idx = blockIdx.x * blockDim.x + threadIdx.x;   // uint4 index
    const int cp = (idx >> 14) & 31;
    const int b  = idx >> 19;
    const int co = cp * 2;
    const float sc0 = g_scale[co],     sh0 = g_shift[co];
    const float sc1 = g_scale[co + 1], sh1 = g_shift[co + 1];
    const uint4 v = reinterpret_cast<const uint4*>(h3)[idx];
    const int off = (idx & 16383) * 4;                       // elem in plane
    float4 o0, o1;
    const uint32_t w[4] = {v.x, v.y, v.z, v.w};
    float r0[4], r1[4];
    #pragma unroll
    for (int j = 0; j < 4; ++j) {
        const __half2 hv = *reinterpret_cast<const __half2*>(&w[j]);
        const float2 f = __half22float2(hv);
        r0[j] = fmaf(f.x, sc0, sh0);
        r1[j] = fmaf(f.y, sc1, sh1);
    }
    o0 = make_float4(r0[0], r0[1], r0[2], r0[3]);
    o1 = make_float4(r1[0], r1[1], r1[2], r1[3]);
    float* p0 = out + ((size_t)b * COUT + co) * H * W + off;
    *reinterpret_cast<float4*>(p0) = o0;
    *reinterpret_cast<float4*>(p0 + (size_t)H * W) = o1;
}

extern "C" void kernel_launch(void* const* d_in, const int* in_sizes, int n_in,
                              void* d_out, int out_size) {
    (void)in_sizes; (void)n_in; (void)out_size;
    const float* x     = (const float*)d_in[0];
    const float* w1    = (const float*)d_in[1];
    const float* w2    = (const float*)d_in[2];
    const float* w3    = (const float*)d_in[3];
    const float* gamma = (const float*)d_in[4];
    const float* beta  = (const float*)d_in[5];
    float* out = (float*)d_out;

    uint32_t *h1, *h2, *h3;
    cudaGetSymbolAddress((void**)&h1, g_h1);
    cudaGetSymbolAddress((void**)&h2, g_h2);
    cudaGetSymbolAddress((void**)&h3, g_h3);

    auto* k1 = conv3x3_tile<CIN0, CMID, 32, 32>;
    auto* k2 = conv_mma<16, 8, 1, 1, 2, false>;   // h1 -> h2 (pair planes)
    auto* k3 = conv_mma<64, 4, 2, 2, 4, true>;    // h2 -> h3 (pair planes)

    constexpr int SM1 = (CIN0 * 34 * 36 + CIN0 * 9 * CMID) * 4;
    constexpr int SM2 = BBASE + 3 * (16 * 112) + 512;   // 31,232
    constexpr int SM3 = BBASE + 3 * (64 * 112) + 512;   // 47,360

    cudaFuncSetAttribute(k1, cudaFuncAttributeMaxDynamicSharedMemorySize, SM1);
    cudaFuncSetAttribute(k2, cudaFuncAttributeMaxDynamicSharedMemorySize, SM2);
    cudaFuncSetAttribute(k3, cudaFuncAttributeMaxDynamicSharedMemorySize, SM3);

    zero_stats_kernel<<<1, 128>>>();
    k1<<<B * (H / 32) * (W / 32), 256, SM1>>>(x, w1, h1);
    k2<<<B * 32 * 2, NT, SM2>>>(h1, w2, h2);
    k3<<<B * 32 * 2, NT, SM3>>>(h2, w3, h3);
    bn_finalize_kernel<<<1, 64>>>(gamma, beta);
    bn_apply_h2_kernel<<<(B * (COUT / 2) * H * W / 4) / 256, 256>>>(h3, out);
}